// round 11
// baseline (speedup 1.0000x reference)
#include <cuda_runtime.h>
#include <math.h>

#define H 512
#define W 512
#define NS 14            // number of gaussian scales (K+1)
#define NK 13            // number of DoG planes (K)
#define MAXR 43
#define NROWS (NK*H)
#define THRESH 0.001f
#define MAXPEAKS 32768

// ---- scratch (static device memory; no allocations allowed) ----
__device__ float2 d_tmp[NS*H*W];      // after horizontal blur (df64 hi/lo)
__device__ float  d_g[NS*H*W];        // gaussian pyramid, fp32 (matches ref's g)
__device__ float  d_kx[NS*96];        // 1D kernels, fp32-rounded coeffs (padded)
__device__ int    d_rad[NS];
__device__ float  d_sig[NS];
__device__ unsigned d_maskw[NROWS*16];// 512-bit peak mask per (k,y) row
                                      // (k=0 and k=12 rows: never written, BSS zero)
__device__ int    d_rowcnt[NROWS];    // exclusive offsets after scan
__device__ int    d_total;            // total peak count

// ---------------------------------------------------------------
// Build normalized 1D gaussian kernels in fp64, round to fp32.
// ---------------------------------------------------------------
__global__ void build_kernels_k(const float* __restrict__ sigma_list) {
    int i   = blockIdx.x;
    int tid = threadIdx.x;      // 128 threads
    float sf = sigma_list[i];
    double s = (double)sf;
    int r   = (int)floor(4.0 * s + 0.5);   // TRUNCATE=4
    int n   = 2 * r + 1;
    __shared__ double tmp[96];
    __shared__ double ssum;
    if (tid < n) {
        double mean = 0.5 * (double)(n - 1);
        double d = ((double)tid - mean) / (2.0 * s);
        tmp[tid] = exp(-(d * d));
    }
    __syncthreads();
    if (tid == 0) {
        double acc = 0.0;
        for (int j = 0; j < n; j++) acc += tmp[j];
        ssum = acc;
        d_rad[i] = r;
        d_sig[i] = sf;
    }
    __syncthreads();
    if (tid < 96) d_kx[i*96 + tid] = (tid < n) ? (float)(tmp[tid] / ssum) : 0.f;
}

// ---------------------------------------------------------------
// Horizontal pass, SYMMETRIC pairing: (a_left + a_right) * k[j].
// Exact-product split + ANCHORED Fast2Sum (hi seeded 2.0).
// 4 outputs/thread. blockDim 128, grid (H, NS).
// ---------------------------------------------------------------
__global__ void hblur_k(const float* __restrict__ x) {
    int y  = blockIdx.x;
    int sc = blockIdx.y;
    int r  = d_rad[sc];
    int n  = 2 * r + 1;
    __shared__ float srow[W + 2*MAXR + 8];
    __shared__ float sk[96];
    int tid = threadIdx.x;
    for (int i = tid; i < W + 2*r + 4; i += 128) {
        int xx = i - r;
        srow[i] = (xx >= 0 && xx < W) ? x[y*W + xx] : 0.f;
    }
    for (int i = tid; i < n; i += 128) sk[i] = d_kx[sc*96 + i];
    __syncthreads();

    int xo = tid * 4;
    float wl[4], wr[4];
    #pragma unroll
    for (int t = 0; t < 4; t++) {
        wl[t] = srow[xo + t];            // left taps, slides forward
        wr[t] = srow[xo + n - 1 + t];    // right taps, slides backward
    }
    float hi[4] = {2.f, 2.f, 2.f, 2.f};
    float lo[4] = {0.f, 0.f, 0.f, 0.f};

    #pragma unroll 4
    for (int j = 0; j < r; j++) {
        float k = sk[j];
        #pragma unroll
        for (int t = 0; t < 4; t++) {
            float s  = __fadd_rn(wl[t], wr[t]);
            float p  = __fmul_rn(s, k);
            float ep = __fmaf_rn(s, k, -p);       // exact product residual
            float t2 = __fadd_rn(hi[t], p);       // Fast2Sum (hi >= 2 > p)
            float e  = __fsub_rn(p, __fsub_rn(t2, hi[t]));
            hi[t] = t2;
            lo[t] = __fadd_rn(lo[t], e);
            lo[t] = __fadd_rn(lo[t], ep);
        }
        wl[0] = wl[1]; wl[1] = wl[2]; wl[2] = wl[3];
        wl[3] = srow[xo + j + 4];
        wr[3] = wr[2]; wr[2] = wr[1]; wr[1] = wr[0];
        wr[0] = srow[xo + n - 2 - j];
    }
    // center tap: wl[t] == srow[xo + r + t] after r slides
    {
        float kc = sk[r];
        #pragma unroll
        for (int t = 0; t < 4; t++) {
            float a  = wl[t];
            float p  = __fmul_rn(a, kc);
            float ep = __fmaf_rn(a, kc, -p);
            float t2 = __fadd_rn(hi[t], p);
            float e  = __fsub_rn(p, __fsub_rn(t2, hi[t]));
            hi[t] = t2;
            lo[t] = __fadd_rn(lo[t], e);
            lo[t] = __fadd_rn(lo[t], ep);
        }
    }
    float2* outp = d_tmp + (size_t)(sc*H + y) * W + xo;
    #pragma unroll
    for (int t = 0; t < 4; t++)
        outp[t] = make_float2(__fsub_rn(hi[t], 2.f), lo[t]);
}

// ---------------------------------------------------------------
// Vertical pass, symmetric pairing on df64 inputs.
// 32-wide x-strip, 32 output rows/block, 4 per thread.
// blockDim (32,8), grid (16,16,NS).
// ---------------------------------------------------------------
#define VTX 32
#define VTY 32
__global__ void vblur_k() {
    int sc = blockIdx.z;
    int x0 = blockIdx.x * VTX;
    int y0 = blockIdx.y * VTY;
    int r  = d_rad[sc];
    int n  = 2 * r + 1;
    __shared__ float2 tile[(VTY + 2*MAXR + 4) * VTX];
    __shared__ float  sk[96];
    int tx  = threadIdx.x;
    int tid = tx + threadIdx.y * VTX;   // 256 threads
    int rows = VTY + 2 * r + 3;
    const float2* inp = d_tmp + (size_t)sc * H * W;
    for (int i = tid; i < rows * VTX; i += 256) {
        int rr = i / VTX, cc = i % VTX;
        int gy = y0 - r + rr;
        tile[i] = (gy >= 0 && gy < H) ? inp[gy*W + x0 + cc] : make_float2(0.f, 0.f);
    }
    for (int i = tid; i < n; i += 256) sk[i] = d_kx[sc*96 + i];
    __syncthreads();

    int yo = threadIdx.y * 4;
    float2 wl[4], wr[4];
    #pragma unroll
    for (int t = 0; t < 4; t++) {
        wl[t] = tile[(yo + t)*VTX + tx];
        wr[t] = tile[(yo + n - 1 + t)*VTX + tx];
    }
    float hi[4] = {2.f, 2.f, 2.f, 2.f};
    float lo[4] = {0.f, 0.f, 0.f, 0.f};

    #pragma unroll 4
    for (int j = 0; j < r; j++) {
        float k = sk[j];
        #pragma unroll
        for (int t = 0; t < 4; t++) {
            float sx = __fadd_rn(wl[t].x, wr[t].x);
            float sy = __fadd_rn(wl[t].y, wr[t].y);
            float p  = __fmul_rn(sx, k);
            float ep = __fmaf_rn(sx, k, -p);
            ep = __fmaf_rn(sy, k, ep);
            float t2 = __fadd_rn(hi[t], p);
            float e  = __fsub_rn(p, __fsub_rn(t2, hi[t]));
            hi[t] = t2;
            lo[t] = __fadd_rn(lo[t], e);
            lo[t] = __fadd_rn(lo[t], ep);
        }
        wl[0] = wl[1]; wl[1] = wl[2]; wl[2] = wl[3];
        wl[3] = tile[(yo + j + 4)*VTX + tx];
        wr[3] = wr[2]; wr[2] = wr[1]; wr[1] = wr[0];
        wr[0] = tile[(yo + n - 2 - j)*VTX + tx];
    }
    // center tap
    {
        float kc = sk[r];
        #pragma unroll
        for (int t = 0; t < 4; t++) {
            float2 a = wl[t];
            float p  = __fmul_rn(a.x, kc);
            float ep = __fmaf_rn(a.x, kc, -p);
            ep = __fmaf_rn(a.y, kc, ep);
            float t2 = __fadd_rn(hi[t], p);
            float e  = __fsub_rn(p, __fsub_rn(t2, hi[t]));
            hi[t] = t2;
            lo[t] = __fadd_rn(lo[t], e);
            lo[t] = __fadd_rn(lo[t], ep);
        }
    }
    float* outp = d_g + (size_t)sc * H * W;
    #pragma unroll
    for (int t = 0; t < 4; t++)
        outp[(y0 + yo + t)*W + x0 + tx] =
            __fadd_rn(__fsub_rn(hi[t], 2.f), lo[t]);
}

// ---------------------------------------------------------------
// FUSED DoG + peak, k-batched with rolling buffers.
// Each block owns a (y,x) tile and a k-group; per k it loads ONE new
// g plane (double-buffered), computes ONE new dog tile (ring of 3),
// then tests the middle plane: c > THRESH && c >= max27 (max27
// includes c) == reference semantics exactly.
// blockDim (32,8), grid (4, 64, 4); k-groups {1-3},{4-6},{7-9},{10,11}.
// ---------------------------------------------------------------
#define PTX 128
#define PTY 8
#define TCOLS (PTX + 2)
#define TROWS (PTY + 2)
__global__ void peak_k() {
    int kt0 = 1 + blockIdx.z * 3;                 // first test plane
    int kt1 = (kt0 + 2 > NK-2) ? (NK-2) : kt0 + 2;// last test plane
    int y0 = blockIdx.y * PTY;
    int x0 = blockIdx.x * PTX;
    __shared__ float gb[2][TROWS][TCOLS];   // g plane double buffer
    __shared__ float dg[3][TROWS][TCOLS];   // dog ring
    __shared__ float vm[PTY][TCOLS];        // 9-way z+vertical max
    int tx = threadIdx.x;
    int ty = threadIdx.y;

    // clamped global coords per covered cell (rows ty, ty+8; cols tx+32q)
    int gy[2], gxc[5];
    #pragma unroll
    for (int rj = 0; rj < 2; rj++) {
        int rr = ty + rj * 8;
        int g = y0 - 1 + rr; if (g < 0) g = 0; if (g > H-1) g = H-1;
        gy[rj] = (rr < TROWS) ? g * W : -1;
    }
    #pragma unroll
    for (int cj = 0; cj < 5; cj++) {
        int cc = tx + cj * 32;
        int g = x0 - 1 + cc; if (g < 0) g = 0; if (g > W-1) g = W-1;
        gxc[cj] = (cc < TCOLS) ? g : -1;
    }

    // prologue: load g[kt0-1], g[kt0]; dog[kt0-1] -> ring[(kt0-1)%3]
    #pragma unroll
    for (int pp = 0; pp < 2; pp++) {
        int kp = kt0 - 1 + pp;
        const float* gp = d_g + (size_t)kp * H * W;
        #pragma unroll
        for (int rj = 0; rj < 2; rj++) {
            if (gy[rj] < 0) continue;
            int rr = ty + rj * 8;
            #pragma unroll
            for (int cj = 0; cj < 5; cj++) {
                if (gxc[cj] < 0) continue;
                gb[kp & 1][rr][tx + cj*32] = gp[gy[rj] + gxc[cj]];
            }
        }
    }
    __syncthreads();
    {
        int kp = kt0 - 1;
        float sg = d_sig[kp];
        #pragma unroll
        for (int rj = 0; rj < 2; rj++) {
            if (gy[rj] < 0) continue;
            int rr = ty + rj * 8;
            #pragma unroll
            for (int cj = 0; cj < 5; cj++) {
                if (gxc[cj] < 0) continue;
                int cc = tx + cj*32;
                dg[kp % 3][rr][cc] = (gb[kp & 1][rr][cc] - gb[(kp+1) & 1][rr][cc]) * sg;
            }
        }
    }

    int y = y0 + ty;
    bool yok = (y >= 1 && y <= H-2);

    // main loop: kk = dog plane being produced; test plane kk-1 when ready
    for (int kk = kt0; kk <= kt1 + 1; kk++) {
        __syncthreads();   // protect ring[kk%3] / gb[(kk+1)&1] from prior readers
        // load g[kk+1] into gb[(kk+1)&1]; compute dog[kk]
        {
            const float* gp = d_g + (size_t)(kk+1) * H * W;
            float sg = d_sig[kk];
            #pragma unroll
            for (int rj = 0; rj < 2; rj++) {
                if (gy[rj] < 0) continue;
                int rr = ty + rj * 8;
                #pragma unroll
                for (int cj = 0; cj < 5; cj++) {
                    if (gxc[cj] < 0) continue;
                    int cc = tx + cj*32;
                    float gv = gp[gy[rj] + gxc[cj]];
                    gb[(kk+1) & 1][rr][cc] = gv;
                    dg[kk % 3][rr][cc] = (gb[kk & 1][rr][cc] - gv) * sg;
                }
            }
        }
        __syncthreads();
        if (kk > kt0) {
            int kt = kk - 1;               // test plane
            int im = (kt - 1) % 3, ic = kt % 3, ip = (kt + 1) % 3;
            // 9-way max: 3 dog planes x 3 rows (rows ty..ty+2), per col
            #pragma unroll
            for (int cj = 0; cj < 5; cj++) {
                if (gxc[cj] < 0) continue;
                int cc = tx + cj*32;
                float m0 = fmaxf(fmaxf(dg[im][ty  ][cc], dg[ic][ty  ][cc]), dg[ip][ty  ][cc]);
                float m1 = fmaxf(fmaxf(dg[im][ty+1][cc], dg[ic][ty+1][cc]), dg[ip][ty+1][cc]);
                float m2 = fmaxf(fmaxf(dg[im][ty+2][cc], dg[ic][ty+2][cc]), dg[ip][ty+2][cc]);
                vm[ty][cc] = fmaxf(fmaxf(m0, m1), m2);
            }
            __syncthreads();
            // horizontal max3 + compare
            #pragma unroll
            for (int q = 0; q < 4; q++) {
                int x  = x0 + q * 32 + tx;
                int lx = q * 32 + tx + 1;
                bool pk = false;
                if (yok && x >= 1 && x <= W-2) {
                    float c = dg[ic][ty+1][lx];
                    if (c > THRESH) {
                        float m = fmaxf(fmaxf(vm[ty][lx-1], vm[ty][lx]), vm[ty][lx+1]);
                        pk = (c >= m);
                    }
                }
                unsigned wmask = __ballot_sync(0xFFFFFFFFu, pk);
                if (tx == 0) d_maskw[(kt*H + y)*16 + (x0/32 + q)] = wmask;
            }
        }
    }
}

// ---------------------------------------------------------------
// Fused count+scan over 6656 rows (row-major order), single block.
// ---------------------------------------------------------------
__global__ void scan_k() {
    const int PER = (NROWS + 1023) / 1024;   // 7
    int tid = threadIdx.x;
    int vals[PER];
    int local = 0;
    int start = tid * PER;
    #pragma unroll
    for (int j = 0; j < PER; j++) {
        int idx = start + j;
        int v = 0;
        if (idx < NROWS) {
            const uint4* mw = (const uint4*)(d_maskw + idx*16);
            #pragma unroll
            for (int q = 0; q < 4; q++) {
                uint4 m = mw[q];
                v += __popc(m.x) + __popc(m.y) + __popc(m.z) + __popc(m.w);
            }
        }
        vals[j] = v;
        local += v;
    }
    __shared__ int sh[1024];
    sh[tid] = local;
    __syncthreads();
    for (int off = 1; off < 1024; off <<= 1) {
        int v = (tid >= off) ? sh[tid - off] : 0;
        __syncthreads();
        sh[tid] += v;
        __syncthreads();
    }
    int run = sh[tid] - local;
    #pragma unroll
    for (int j = 0; j < PER; j++) {
        int idx = start + j;
        if (idx < NROWS) { d_rowcnt[idx] = run; run += vals[j]; }
    }
    if (tid == 1023) d_total = sh[1023];
}

// ---------------------------------------------------------------
// Fused fill + scatter (disjoint index ranges, order-independent).
// grid NROWS blocks of 32 threads.
// ---------------------------------------------------------------
__global__ void write_k(float* __restrict__ out) {
    int rid  = blockIdx.x;
    int lane = threadIdx.x;
    int total = d_total;
    float sig0 = d_sig[0];
    #pragma unroll
    for (int j = 0; j < 5; j++) {          // 5*NROWS = 33280 >= MAXPEAKS
        int f = rid + j * NROWS;
        if (f < MAXPEAKS && f >= total && lane < 3)
            out[3*f + lane] = (lane == 0) ? sig0 : 0.f;
    }
    int k = rid >> 9, y = rid & 511;
    int run = d_rowcnt[rid];
    float sg = d_sig[k];
    for (int w = 0; w < 16; w++) {
        unsigned word = d_maskw[rid*16 + w];
        if (word) {
            if ((word >> lane) & 1u) {
                int idx = run + __popc(word & ((1u << lane) - 1u));
                if (idx < MAXPEAKS) {
                    out[3*idx]     = sg;
                    out[3*idx + 1] = (float)y;
                    out[3*idx + 2] = (float)(w*32 + lane);
                }
            }
            run += __popc(word);
        }
    }
}

extern "C" void kernel_launch(void* const* d_in, const int* in_sizes, int n_in,
                              void* d_out, int out_size) {
    const float* x     = nullptr;
    const float* sigma = nullptr;
    for (int i = 0; i < n_in; i++) {
        if (in_sizes[i] == H * W)   x     = (const float*)d_in[i];
        else if (in_sizes[i] == NS) sigma = (const float*)d_in[i];
    }
    if (!x)     x     = (const float*)d_in[0];
    if (!sigma) sigma = (const float*)d_in[n_in - 1];

    float* out = (float*)d_out;                   // [32768, 3]

    build_kernels_k<<<NS, 128>>>(sigma);
    hblur_k<<<dim3(H, NS), 128>>>(x);
    vblur_k<<<dim3(W/VTX, H/VTY, NS), dim3(VTX, 8)>>>();
    peak_k<<<dim3(W/PTX, H/PTY, 4), dim3(32, 8)>>>();
    scan_k<<<1, 1024>>>();
    write_k<<<NROWS, 32>>>(out);
}

// round 12
// speedup vs baseline: 1.2273x; 1.2273x over previous
#include <cuda_runtime.h>
#include <math.h>

#define H 512
#define W 512
#define NS 14            // number of gaussian scales (K+1)
#define NK 13            // number of DoG planes (K)
#define MAXR 43
#define NROWS (NK*H)
#define THRESH 0.001f
#define MAXPEAKS 32768

// ---- scratch (static device memory; no allocations allowed) ----
__device__ float  d_tmpf[NS*H*W];     // after horizontal blur (fp32-rounded)
__device__ float  d_g[NS*H*W];        // gaussian pyramid, fp32 (matches ref's g)
__device__ float  d_kx[NS*96];        // 1D kernels, fp32-rounded coeffs (padded)
__device__ int    d_rad[NS];
__device__ float  d_sig[NS];
__device__ unsigned d_maskw[NROWS*16];// 512-bit peak mask per (k,y) row
                                      // (k=0 and k=12 rows: never written, BSS zero)
__device__ int    d_pcnt[NROWS*4];    // per-(row, x-block) popcounts (k=0/12: BSS zero)
__device__ int    d_rowcnt[NROWS];    // exclusive offsets after scan
__device__ int    d_total;            // total peak count

// ---------------------------------------------------------------
// Build normalized 1D gaussian kernels in fp64, round to fp32.
// ---------------------------------------------------------------
__global__ void build_kernels_k(const float* __restrict__ sigma_list) {
    int i   = blockIdx.x;
    int tid = threadIdx.x;      // 128 threads
    float sf = sigma_list[i];
    double s = (double)sf;
    int r   = (int)floor(4.0 * s + 0.5);   // TRUNCATE=4
    int n   = 2 * r + 1;
    __shared__ double tmp[96];
    __shared__ double ssum;
    if (tid < n) {
        double mean = 0.5 * (double)(n - 1);
        double d = ((double)tid - mean) / (2.0 * s);
        tmp[tid] = exp(-(d * d));
    }
    __syncthreads();
    if (tid == 0) {
        double acc = 0.0;
        for (int j = 0; j < n; j++) acc += tmp[j];
        ssum = acc;
        d_rad[i] = r;
        d_sig[i] = sf;
    }
    __syncthreads();
    if (tid < 96) d_kx[i*96 + tid] = (tid < n) ? (float)(tmp[tid] / ssum) : 0.f;
}

// ---------------------------------------------------------------
// Horizontal pass, SYMMETRIC pairing: (a_left + a_right) * k[j].
// Exact-product split + ANCHORED Fast2Sum (hi seeded 2.0).
// Output rounded once to fp32 (error <= 6e-8 relative, same class
// as validated coefficient rounding). 4 outputs/thread -> float4.
// blockDim 128, grid (H, NS).
// ---------------------------------------------------------------
__global__ void hblur_k(const float* __restrict__ x) {
    int y  = blockIdx.x;
    int sc = blockIdx.y;
    int r  = d_rad[sc];
    int n  = 2 * r + 1;
    __shared__ float srow[W + 2*MAXR + 8];
    __shared__ float sk[96];
    int tid = threadIdx.x;
    for (int i = tid; i < W + 2*r + 4; i += 128) {
        int xx = i - r;
        srow[i] = (xx >= 0 && xx < W) ? x[y*W + xx] : 0.f;
    }
    for (int i = tid; i < n; i += 128) sk[i] = d_kx[sc*96 + i];
    __syncthreads();

    int xo = tid * 4;
    float wl[4], wr[4];
    #pragma unroll
    for (int t = 0; t < 4; t++) {
        wl[t] = srow[xo + t];            // left taps, slides forward
        wr[t] = srow[xo + n - 1 + t];    // right taps, slides backward
    }
    float hi[4] = {2.f, 2.f, 2.f, 2.f};
    float lo[4] = {0.f, 0.f, 0.f, 0.f};

    #pragma unroll 4
    for (int j = 0; j < r; j++) {
        float k = sk[j];
        #pragma unroll
        for (int t = 0; t < 4; t++) {
            float s  = __fadd_rn(wl[t], wr[t]);
            float p  = __fmul_rn(s, k);
            float ep = __fmaf_rn(s, k, -p);       // exact product residual
            float t2 = __fadd_rn(hi[t], p);       // Fast2Sum (hi >= 2 > p)
            float e  = __fsub_rn(p, __fsub_rn(t2, hi[t]));
            hi[t] = t2;
            lo[t] = __fadd_rn(lo[t], e);
            lo[t] = __fadd_rn(lo[t], ep);
        }
        wl[0] = wl[1]; wl[1] = wl[2]; wl[2] = wl[3];
        wl[3] = srow[xo + j + 4];
        wr[3] = wr[2]; wr[2] = wr[1]; wr[1] = wr[0];
        wr[0] = srow[xo + n - 2 - j];
    }
    // center tap: wl[t] == srow[xo + r + t] after r slides
    {
        float kc = sk[r];
        #pragma unroll
        for (int t = 0; t < 4; t++) {
            float a  = wl[t];
            float p  = __fmul_rn(a, kc);
            float ep = __fmaf_rn(a, kc, -p);
            float t2 = __fadd_rn(hi[t], p);
            float e  = __fsub_rn(p, __fsub_rn(t2, hi[t]));
            hi[t] = t2;
            lo[t] = __fadd_rn(lo[t], e);
            lo[t] = __fadd_rn(lo[t], ep);
        }
    }
    float4 o;
    o.x = __fadd_rn(__fsub_rn(hi[0], 2.f), lo[0]);
    o.y = __fadd_rn(__fsub_rn(hi[1], 2.f), lo[1]);
    o.z = __fadd_rn(__fsub_rn(hi[2], 2.f), lo[2]);
    o.w = __fadd_rn(__fsub_rn(hi[3], 2.f), lo[3]);
    *(float4*)(d_tmpf + (size_t)(sc*H + y) * W + xo) = o;
}

// ---------------------------------------------------------------
// Vertical pass, symmetric pairing on fp32 inputs (same scheme as H).
// 32-wide x-strip, 32 output rows/block, 4 per thread.
// blockDim (32,8), grid (16,16,NS).
// ---------------------------------------------------------------
#define VTX 32
#define VTY 32
__global__ void vblur_k() {
    int sc = blockIdx.z;
    int x0 = blockIdx.x * VTX;
    int y0 = blockIdx.y * VTY;
    int r  = d_rad[sc];
    int n  = 2 * r + 1;
    __shared__ float tile[(VTY + 2*MAXR + 4) * VTX];
    __shared__ float sk[96];
    int tx  = threadIdx.x;
    int tid = tx + threadIdx.y * VTX;   // 256 threads
    int rows = VTY + 2 * r + 3;
    const float* inp = d_tmpf + (size_t)sc * H * W;
    for (int i = tid; i < rows * VTX; i += 256) {
        int rr = i / VTX, cc = i % VTX;
        int gy = y0 - r + rr;
        tile[i] = (gy >= 0 && gy < H) ? inp[gy*W + x0 + cc] : 0.f;
    }
    for (int i = tid; i < n; i += 256) sk[i] = d_kx[sc*96 + i];
    __syncthreads();

    int yo = threadIdx.y * 4;
    float wl[4], wr[4];
    #pragma unroll
    for (int t = 0; t < 4; t++) {
        wl[t] = tile[(yo + t)*VTX + tx];
        wr[t] = tile[(yo + n - 1 + t)*VTX + tx];
    }
    float hi[4] = {2.f, 2.f, 2.f, 2.f};
    float lo[4] = {0.f, 0.f, 0.f, 0.f};

    #pragma unroll 4
    for (int j = 0; j < r; j++) {
        float k = sk[j];
        #pragma unroll
        for (int t = 0; t < 4; t++) {
            float s  = __fadd_rn(wl[t], wr[t]);
            float p  = __fmul_rn(s, k);
            float ep = __fmaf_rn(s, k, -p);
            float t2 = __fadd_rn(hi[t], p);
            float e  = __fsub_rn(p, __fsub_rn(t2, hi[t]));
            hi[t] = t2;
            lo[t] = __fadd_rn(lo[t], e);
            lo[t] = __fadd_rn(lo[t], ep);
        }
        wl[0] = wl[1]; wl[1] = wl[2]; wl[2] = wl[3];
        wl[3] = tile[(yo + j + 4)*VTX + tx];
        wr[3] = wr[2]; wr[2] = wr[1]; wr[1] = wr[0];
        wr[0] = tile[(yo + n - 2 - j)*VTX + tx];
    }
    // center tap
    {
        float kc = sk[r];
        #pragma unroll
        for (int t = 0; t < 4; t++) {
            float a  = wl[t];
            float p  = __fmul_rn(a, kc);
            float ep = __fmaf_rn(a, kc, -p);
            float t2 = __fadd_rn(hi[t], p);
            float e  = __fsub_rn(p, __fsub_rn(t2, hi[t]));
            hi[t] = t2;
            lo[t] = __fadd_rn(lo[t], e);
            lo[t] = __fadd_rn(lo[t], ep);
        }
    }
    float* outp = d_g + (size_t)sc * H * W;
    #pragma unroll
    for (int t = 0; t < 4; t++)
        outp[(y0 + yo + t)*W + x0 + tx] =
            __fadd_rn(__fsub_rn(hi[t], 2.f), lo[t]);
}

// ---------------------------------------------------------------
// FUSED DoG + peak, separable max-pool formulation (R10 version).
// pk = (c > THRESH) && (c >= max27), max27 includes c == reference.
// Also emits per-(row, x-block) popcounts (plain stores, replay-safe).
// blockDim (32,8), grid (4, 64, NK-2).
// ---------------------------------------------------------------
#define PTX 128
#define PTY 8
#define TCOLS (PTX + 2)
__global__ void peak_k() {
    int k  = blockIdx.z + 1;            // 1..11
    int y0 = blockIdx.y * PTY;
    int x0 = blockIdx.x * PTX;
    __shared__ float szmax[PTY + 2][TCOLS];
    __shared__ float sdogc[PTY + 2][TCOLS];
    __shared__ float svmax[PTY][TCOLS];
    int tx = threadIdx.x;
    int ty = threadIdx.y;

    float sgm1 = d_sig[k-1], sg0 = d_sig[k], sgp1 = d_sig[k+1];
    const float* gm1 = d_g + (size_t)(k-1) * H * W;
    const float* g0  = gm1 + H * W;
    const float* gp1 = g0  + H * W;
    const float* gp2 = gp1 + H * W;

    // fill: dog for 3 planes from 4 g loads; zmax + center dog stored
    #pragma unroll
    for (int rr = ty; rr < PTY + 2; rr += 8) {
        int gy = y0 - 1 + rr; if (gy < 0) gy = 0; if (gy > H-1) gy = H-1;
        int gyW = gy * W;
        #pragma unroll
        for (int cc = tx; cc < TCOLS; cc += 32) {
            int gx = x0 - 1 + cc; if (gx > W-1) gx = W-1;
            if (gx < 0) gx = 0;
            int gi = gyW + gx;
            float a = gm1[gi], b = g0[gi], c = gp1[gi], d = gp2[gi];
            float dm1 = (a - b) * sgm1;
            float dc  = (b - c) * sg0;
            float dp1 = (c - d) * sgp1;
            szmax[rr][cc] = fmaxf(fmaxf(dm1, dc), dp1);
            sdogc[rr][cc] = dc;
        }
    }
    __syncthreads();

    // vertical max3
    #pragma unroll
    for (int cc = tx; cc < TCOLS; cc += 32)
        svmax[ty][cc] = fmaxf(fmaxf(szmax[ty][cc], szmax[ty+1][cc]),
                              szmax[ty+2][cc]);
    __syncthreads();

    // horizontal max3 + compare
    int y = y0 + ty;
    int cnt = 0;
    #pragma unroll
    for (int q = 0; q < 4; q++) {
        int x  = x0 + q * 32 + tx;
        int lx = q * 32 + tx + 1;
        bool pk = false;
        if (y >= 1 && y <= H-2 && x >= 1 && x <= W-2) {
            float c = sdogc[ty+1][lx];
            if (c > THRESH) {
                float m = fmaxf(fmaxf(svmax[ty][lx-1], svmax[ty][lx]),
                                svmax[ty][lx+1]);
                pk = (c >= m);
            }
        }
        unsigned wmask = __ballot_sync(0xFFFFFFFFu, pk);
        if (tx == 0) {
            d_maskw[(k*H + y)*16 + (x0/32 + q)] = wmask;
            cnt += __popc(wmask);
        }
    }
    if (tx == 0) d_pcnt[(k*H + y)*4 + blockIdx.x] = cnt;
}

// ---------------------------------------------------------------
// Count+scan over 6656 rows from the small per-block count array.
// ---------------------------------------------------------------
__global__ void scan_k() {
    const int PER = (NROWS + 1023) / 1024;   // 7
    int tid = threadIdx.x;
    int vals[PER];
    int local = 0;
    int start = tid * PER;
    #pragma unroll
    for (int j = 0; j < PER; j++) {
        int idx = start + j;
        int v = 0;
        if (idx < NROWS) {
            int4 c = *(const int4*)(d_pcnt + idx*4);
            v = c.x + c.y + c.z + c.w;
        }
        vals[j] = v;
        local += v;
    }
    __shared__ int sh[1024];
    sh[tid] = local;
    __syncthreads();
    for (int off = 1; off < 1024; off <<= 1) {
        int v = (tid >= off) ? sh[tid - off] : 0;
        __syncthreads();
        sh[tid] += v;
        __syncthreads();
    }
    int run = sh[tid] - local;
    #pragma unroll
    for (int j = 0; j < PER; j++) {
        int idx = start + j;
        if (idx < NROWS) { d_rowcnt[idx] = run; run += vals[j]; }
    }
    if (tid == 1023) d_total = sh[1023];
}

// ---------------------------------------------------------------
// Fused fill + scatter (disjoint index ranges, order-independent).
// grid NROWS blocks of 32 threads.
// ---------------------------------------------------------------
__global__ void write_k(float* __restrict__ out) {
    int rid  = blockIdx.x;
    int lane = threadIdx.x;
    int total = d_total;
    float sig0 = d_sig[0];
    #pragma unroll
    for (int j = 0; j < 5; j++) {          // 5*NROWS = 33280 >= MAXPEAKS
        int f = rid + j * NROWS;
        if (f < MAXPEAKS && f >= total && lane < 3)
            out[3*f + lane] = (lane == 0) ? sig0 : 0.f;
    }
    int k = rid >> 9, y = rid & 511;
    int run = d_rowcnt[rid];
    float sg = d_sig[k];
    for (int w = 0; w < 16; w++) {
        unsigned word = d_maskw[rid*16 + w];
        if (word) {
            if ((word >> lane) & 1u) {
                int idx = run + __popc(word & ((1u << lane) - 1u));
                if (idx < MAXPEAKS) {
                    out[3*idx]     = sg;
                    out[3*idx + 1] = (float)y;
                    out[3*idx + 2] = (float)(w*32 + lane);
                }
            }
            run += __popc(word);
        }
    }
}

extern "C" void kernel_launch(void* const* d_in, const int* in_sizes, int n_in,
                              void* d_out, int out_size) {
    const float* x     = nullptr;
    const float* sigma = nullptr;
    for (int i = 0; i < n_in; i++) {
        if (in_sizes[i] == H * W)   x     = (const float*)d_in[i];
        else if (in_sizes[i] == NS) sigma = (const float*)d_in[i];
    }
    if (!x)     x     = (const float*)d_in[0];
    if (!sigma) sigma = (const float*)d_in[n_in - 1];

    float* out = (float*)d_out;                   // [32768, 3]

    build_kernels_k<<<NS, 128>>>(sigma);
    hblur_k<<<dim3(H, NS), 128>>>(x);
    vblur_k<<<dim3(W/VTX, H/VTY, NS), dim3(VTX, 8)>>>();
    peak_k<<<dim3(W/PTX, H/PTY, NK-2), dim3(32, 8)>>>();
    scan_k<<<1, 1024>>>();
    write_k<<<NROWS, 32>>>(out);
}

// round 13
// speedup vs baseline: 1.4679x; 1.1960x over previous
#include <cuda_runtime.h>
#include <math.h>

#define H 512
#define W 512
#define NS 14            // number of gaussian scales (K+1)
#define NK 13            // number of DoG planes (K)
#define MAXR 43
#define NROWS (NK*H)
#define THRESH 0.001f
#define MAXPEAKS 32768

// ---- scratch (static device memory; no allocations allowed) ----
__device__ float  d_tmpf[NS*H*W];     // after horizontal blur (fp32-rounded)
__device__ float  d_g[NS*H*W];        // gaussian pyramid, fp32 (matches ref's g)
__device__ float  d_kx[NS*96];        // 1D kernels, fp32-rounded coeffs (padded)
__device__ int    d_rad[NS];
__device__ float  d_sig[NS];
__device__ unsigned d_maskw[NROWS*16];// 512-bit peak mask per (k,y) row
                                      // (k=0 and k=12 rows: never written, BSS zero)
__device__ int    d_pcnt[NROWS*4];    // per-(row, x-block) popcounts (k=0/12: BSS zero)
__device__ int    d_rowcnt[NROWS];    // exclusive offsets after scan
__device__ int    d_total;            // total peak count

// Anchored Fast2Sum: hi >= 2 > b >= 0 always -> error extraction exact.
#define F2S(hi_, lo_, b_) do { \
    float t2_ = __fadd_rn(hi_, b_); \
    float u_  = __fsub_rn(t2_, hi_); \
    float e_  = __fsub_rn(b_, u_); \
    hi_ = t2_; \
    lo_ = __fadd_rn(lo_, e_); \
} while (0)

// ---------------------------------------------------------------
// Build normalized 1D gaussian kernels in fp64, round to fp32.
// ---------------------------------------------------------------
__global__ void build_kernels_k(const float* __restrict__ sigma_list) {
    int i   = blockIdx.x;
    int tid = threadIdx.x;      // 128 threads
    float sf = sigma_list[i];
    double s = (double)sf;
    int r   = (int)floor(4.0 * s + 0.5);   // TRUNCATE=4
    int n   = 2 * r + 1;
    __shared__ double tmp[96];
    __shared__ double ssum;
    if (tid < n) {
        double mean = 0.5 * (double)(n - 1);
        double d = ((double)tid - mean) / (2.0 * s);
        tmp[tid] = exp(-(d * d));
    }
    __syncthreads();
    if (tid == 0) {
        double acc = 0.0;
        for (int j = 0; j < n; j++) acc += tmp[j];
        ssum = acc;
        d_rad[i] = r;
        d_sig[i] = sf;
    }
    __syncthreads();
    if (tid < 96) d_kx[i*96 + tid] = (tid < n) ? (float)(tmp[tid] / ssum) : 0.f;
}

// ---------------------------------------------------------------
// Horizontal pass. Symmetric pairing (a_l+a_r)*k, TWO pairs folded
// per anchored Fast2Sum (block-compensated): per block
//   b = s1*k0 + s2*k1  (mul + fma, <=2 partial-sum roundings)
//   Fast2Sum(hi=2-anchored, lo, b)  (addition error captured exactly)
// 2 fma-ops/tap. 5-wide sliding windows, step 2. 4 outputs/thread.
// blockDim 128, grid (H, NS).
// ---------------------------------------------------------------
__global__ void hblur_k(const float* __restrict__ x) {
    int y  = blockIdx.x;
    int sc = blockIdx.y;
    int r  = d_rad[sc];
    int n  = 2 * r + 1;
    __shared__ float srow[W + 2*MAXR + 8];
    __shared__ float sk[96];
    int tid = threadIdx.x;
    for (int i = tid; i < W + 2*r + 4; i += 128) {
        int xx = i - r;
        srow[i] = (xx >= 0 && xx < W) ? x[y*W + xx] : 0.f;
    }
    for (int i = tid; i < n; i += 128) sk[i] = d_kx[sc*96 + i];
    __syncthreads();

    int xo = tid * 4;
    float wl[5], wr[5];
    #pragma unroll
    for (int q = 0; q < 5; q++) {
        wl[q] = srow[xo + q];            // left:  srow[xo + j + q]
        wr[q] = srow[xo + n - 2 + q];    // right: srow[xo + n-2-j + q]
    }
    float hi[4] = {2.f, 2.f, 2.f, 2.f};
    float lo[4] = {0.f, 0.f, 0.f, 0.f};

    int j = 0;
    #pragma unroll 2
    for (; j + 1 < r; j += 2) {
        float k0 = sk[j], k1 = sk[j+1];
        #pragma unroll
        for (int t = 0; t < 4; t++) {
            float s1 = __fadd_rn(wl[t],   wr[t+1]);   // pair j
            float b  = __fmul_rn(s1, k0);
            float s2 = __fadd_rn(wl[t+1], wr[t]);     // pair j+1
            b = __fmaf_rn(s2, k1, b);
            F2S(hi[t], lo[t], b);
        }
        wl[0] = wl[2]; wl[1] = wl[3]; wl[2] = wl[4];
        wl[3] = srow[xo + j + 5];
        wl[4] = srow[xo + j + 6];
        wr[4] = wr[2]; wr[3] = wr[1]; wr[2] = wr[0];
        wr[0] = srow[xo + n - 4 - j];
        wr[1] = srow[xo + n - 3 - j];
    }
    if (r & 1) {
        float kj = sk[r-1];                           // leftover pair j=r-1
        float kc = sk[r];
        #pragma unroll
        for (int t = 0; t < 4; t++) {
            float s = __fadd_rn(wl[t], wr[t+1]);
            float b = __fmul_rn(s, kj);
            b = __fmaf_rn(wl[t+1], kc, b);            // + center tap
            F2S(hi[t], lo[t], b);
        }
    } else {
        float kc = sk[r];
        #pragma unroll
        for (int t = 0; t < 4; t++) {
            float b = __fmul_rn(wl[t], kc);           // center tap
            F2S(hi[t], lo[t], b);
        }
    }
    float4 o;
    o.x = __fadd_rn(__fsub_rn(hi[0], 2.f), lo[0]);
    o.y = __fadd_rn(__fsub_rn(hi[1], 2.f), lo[1]);
    o.z = __fadd_rn(__fsub_rn(hi[2], 2.f), lo[2]);
    o.w = __fadd_rn(__fsub_rn(hi[3], 2.f), lo[3]);
    *(float4*)(d_tmpf + (size_t)(sc*H + y) * W + xo) = o;
}

// ---------------------------------------------------------------
// Vertical pass, same block-compensated scheme on fp32 inputs.
// 32-wide x-strip, 32 output rows/block, 4 per thread.
// blockDim (32,8), grid (16,16,NS).
// ---------------------------------------------------------------
#define VTX 32
#define VTY 32
__global__ void vblur_k() {
    int sc = blockIdx.z;
    int x0 = blockIdx.x * VTX;
    int y0 = blockIdx.y * VTY;
    int r  = d_rad[sc];
    int n  = 2 * r + 1;
    __shared__ float tile[(VTY + 2*MAXR + 4) * VTX];
    __shared__ float sk[96];
    int tx  = threadIdx.x;
    int tid = tx + threadIdx.y * VTX;   // 256 threads
    int rows = VTY + 2 * r + 3;
    const float* inp = d_tmpf + (size_t)sc * H * W;
    for (int i = tid; i < rows * VTX; i += 256) {
        int rr = i / VTX, cc = i % VTX;
        int gy = y0 - r + rr;
        tile[i] = (gy >= 0 && gy < H) ? inp[gy*W + x0 + cc] : 0.f;
    }
    for (int i = tid; i < n; i += 256) sk[i] = d_kx[sc*96 + i];
    __syncthreads();

    int yo = threadIdx.y * 4;
    float wl[5], wr[5];
    #pragma unroll
    for (int q = 0; q < 5; q++) {
        wl[q] = tile[(yo + q)*VTX + tx];
        wr[q] = tile[(yo + n - 2 + q)*VTX + tx];
    }
    float hi[4] = {2.f, 2.f, 2.f, 2.f};
    float lo[4] = {0.f, 0.f, 0.f, 0.f};

    int j = 0;
    #pragma unroll 2
    for (; j + 1 < r; j += 2) {
        float k0 = sk[j], k1 = sk[j+1];
        #pragma unroll
        for (int t = 0; t < 4; t++) {
            float s1 = __fadd_rn(wl[t],   wr[t+1]);
            float b  = __fmul_rn(s1, k0);
            float s2 = __fadd_rn(wl[t+1], wr[t]);
            b = __fmaf_rn(s2, k1, b);
            F2S(hi[t], lo[t], b);
        }
        wl[0] = wl[2]; wl[1] = wl[3]; wl[2] = wl[4];
        wl[3] = tile[(yo + j + 5)*VTX + tx];
        wl[4] = tile[(yo + j + 6)*VTX + tx];
        wr[4] = wr[2]; wr[3] = wr[1]; wr[2] = wr[0];
        wr[0] = tile[(yo + n - 4 - j)*VTX + tx];
        wr[1] = tile[(yo + n - 3 - j)*VTX + tx];
    }
    if (r & 1) {
        float kj = sk[r-1];
        float kc = sk[r];
        #pragma unroll
        for (int t = 0; t < 4; t++) {
            float s = __fadd_rn(wl[t], wr[t+1]);
            float b = __fmul_rn(s, kj);
            b = __fmaf_rn(wl[t+1], kc, b);
            F2S(hi[t], lo[t], b);
        }
    } else {
        float kc = sk[r];
        #pragma unroll
        for (int t = 0; t < 4; t++) {
            float b = __fmul_rn(wl[t], kc);
            F2S(hi[t], lo[t], b);
        }
    }
    float* outp = d_g + (size_t)sc * H * W;
    #pragma unroll
    for (int t = 0; t < 4; t++)
        outp[(y0 + yo + t)*W + x0 + tx] =
            __fadd_rn(__fsub_rn(hi[t], 2.f), lo[t]);
}

// ---------------------------------------------------------------
// FUSED DoG + peak, separable max-pool formulation.
// pk = (c > THRESH) && (c >= max27), max27 includes c == reference.
// Emits per-(row, x-block) popcounts (plain stores, replay-safe).
// blockDim (32,8), grid (4, 64, NK-2).
// ---------------------------------------------------------------
#define PTX 128
#define PTY 8
#define TCOLS (PTX + 2)
__global__ void peak_k() {
    int k  = blockIdx.z + 1;            // 1..11
    int y0 = blockIdx.y * PTY;
    int x0 = blockIdx.x * PTX;
    __shared__ float szmax[PTY + 2][TCOLS];
    __shared__ float sdogc[PTY + 2][TCOLS];
    __shared__ float svmax[PTY][TCOLS];
    int tx = threadIdx.x;
    int ty = threadIdx.y;

    float sgm1 = d_sig[k-1], sg0 = d_sig[k], sgp1 = d_sig[k+1];
    const float* gm1 = d_g + (size_t)(k-1) * H * W;
    const float* g0  = gm1 + H * W;
    const float* gp1 = g0  + H * W;
    const float* gp2 = gp1 + H * W;

    #pragma unroll
    for (int rr = ty; rr < PTY + 2; rr += 8) {
        int gy = y0 - 1 + rr; if (gy < 0) gy = 0; if (gy > H-1) gy = H-1;
        int gyW = gy * W;
        #pragma unroll
        for (int cc = tx; cc < TCOLS; cc += 32) {
            int gx = x0 - 1 + cc; if (gx > W-1) gx = W-1;
            if (gx < 0) gx = 0;
            int gi = gyW + gx;
            float a = gm1[gi], b = g0[gi], c = gp1[gi], d = gp2[gi];
            float dm1 = (a - b) * sgm1;
            float dc  = (b - c) * sg0;
            float dp1 = (c - d) * sgp1;
            szmax[rr][cc] = fmaxf(fmaxf(dm1, dc), dp1);
            sdogc[rr][cc] = dc;
        }
    }
    __syncthreads();

    #pragma unroll
    for (int cc = tx; cc < TCOLS; cc += 32)
        svmax[ty][cc] = fmaxf(fmaxf(szmax[ty][cc], szmax[ty+1][cc]),
                              szmax[ty+2][cc]);
    __syncthreads();

    int y = y0 + ty;
    int cnt = 0;
    #pragma unroll
    for (int q = 0; q < 4; q++) {
        int x  = x0 + q * 32 + tx;
        int lx = q * 32 + tx + 1;
        bool pk = false;
        if (y >= 1 && y <= H-2 && x >= 1 && x <= W-2) {
            float c = sdogc[ty+1][lx];
            if (c > THRESH) {
                float m = fmaxf(fmaxf(svmax[ty][lx-1], svmax[ty][lx]),
                                svmax[ty][lx+1]);
                pk = (c >= m);
            }
        }
        unsigned wmask = __ballot_sync(0xFFFFFFFFu, pk);
        if (tx == 0) {
            d_maskw[(k*H + y)*16 + (x0/32 + q)] = wmask;
            cnt += __popc(wmask);
        }
    }
    if (tx == 0) d_pcnt[(k*H + y)*4 + blockIdx.x] = cnt;
}

// ---------------------------------------------------------------
// Count+scan over 6656 rows from the small per-block count array.
// ---------------------------------------------------------------
__global__ void scan_k() {
    const int PER = (NROWS + 1023) / 1024;   // 7
    int tid = threadIdx.x;
    int vals[PER];
    int local = 0;
    int start = tid * PER;
    #pragma unroll
    for (int j = 0; j < PER; j++) {
        int idx = start + j;
        int v = 0;
        if (idx < NROWS) {
            int4 c = *(const int4*)(d_pcnt + idx*4);
            v = c.x + c.y + c.z + c.w;
        }
        vals[j] = v;
        local += v;
    }
    __shared__ int sh[1024];
    sh[tid] = local;
    __syncthreads();
    for (int off = 1; off < 1024; off <<= 1) {
        int v = (tid >= off) ? sh[tid - off] : 0;
        __syncthreads();
        sh[tid] += v;
        __syncthreads();
    }
    int run = sh[tid] - local;
    #pragma unroll
    for (int j = 0; j < PER; j++) {
        int idx = start + j;
        if (idx < NROWS) { d_rowcnt[idx] = run; run += vals[j]; }
    }
    if (tid == 1023) d_total = sh[1023];
}

// ---------------------------------------------------------------
// Fused fill + scatter (disjoint index ranges, order-independent).
// grid NROWS blocks of 32 threads.
// ---------------------------------------------------------------
__global__ void write_k(float* __restrict__ out) {
    int rid  = blockIdx.x;
    int lane = threadIdx.x;
    int total = d_total;
    float sig0 = d_sig[0];
    #pragma unroll
    for (int j = 0; j < 5; j++) {          // 5*NROWS = 33280 >= MAXPEAKS
        int f = rid + j * NROWS;
        if (f < MAXPEAKS && f >= total && lane < 3)
            out[3*f + lane] = (lane == 0) ? sig0 : 0.f;
    }
    int k = rid >> 9, y = rid & 511;
    int run = d_rowcnt[rid];
    float sg = d_sig[k];
    for (int w = 0; w < 16; w++) {
        unsigned word = d_maskw[rid*16 + w];
        if (word) {
            if ((word >> lane) & 1u) {
                int idx = run + __popc(word & ((1u << lane) - 1u));
                if (idx < MAXPEAKS) {
                    out[3*idx]     = sg;
                    out[3*idx + 1] = (float)y;
                    out[3*idx + 2] = (float)(w*32 + lane);
                }
            }
            run += __popc(word);
        }
    }
}

extern "C" void kernel_launch(void* const* d_in, const int* in_sizes, int n_in,
                              void* d_out, int out_size) {
    const float* x     = nullptr;
    const float* sigma = nullptr;
    for (int i = 0; i < n_in; i++) {
        if (in_sizes[i] == H * W)   x     = (const float*)d_in[i];
        else if (in_sizes[i] == NS) sigma = (const float*)d_in[i];
    }
    if (!x)     x     = (const float*)d_in[0];
    if (!sigma) sigma = (const float*)d_in[n_in - 1];

    float* out = (float*)d_out;                   // [32768, 3]

    build_kernels_k<<<NS, 128>>>(sigma);
    hblur_k<<<dim3(H, NS), 128>>>(x);
    vblur_k<<<dim3(W/VTX, H/VTY, NS), dim3(VTX, 8)>>>();
    peak_k<<<dim3(W/PTX, H/PTY, NK-2), dim3(32, 8)>>>();
    scan_k<<<1, 1024>>>();
    write_k<<<NROWS, 32>>>(out);
}

// round 14
// speedup vs baseline: 1.5102x; 1.0288x over previous
#include <cuda_runtime.h>
#include <math.h>

#define H 512
#define W 512
#define NS 14            // number of gaussian scales (K+1)
#define NK 13            // number of DoG planes (K)
#define MAXR 43
#define NROWS (NK*H)
#define THRESH 0.001f
#define MAXPEAKS 32768
#define HW (H*W)

// ---- scratch (static device memory; no allocations allowed) ----
__device__ float  d_tmpf[NS*H*W];     // after horizontal blur (fp32-rounded)
// g pyramid with 1024-float guard pads on both sides so peak_k can read
// halo cells unclamped (garbage values there are only consumed as
// neighbors of border-excluded pixels -> never affect results).
__device__ __align__(16) float d_gbuf[NS*H*W + 2048];
#define D_G (d_gbuf + 1024)
__device__ float  d_kx[NS*96];        // 1D kernels, fp32-rounded coeffs (padded)
__device__ int    d_rad[NS];
__device__ float  d_sig[NS];
__device__ unsigned d_maskw[NROWS*16];// 512-bit peak mask per (k,y) row
                                      // (k=0 and k=12 rows: never written, BSS zero)
__device__ int    d_pcnt[NROWS*4];    // per-(row, x-block) popcounts (k=0/12: BSS zero)
__device__ int    d_rowcnt[NROWS];    // exclusive offsets after scan
__device__ int    d_total;            // total peak count

// Anchored Fast2Sum: hi >= 2 > b >= 0 always -> error extraction exact.
#define F2S(hi_, lo_, b_) do { \
    float t2_ = __fadd_rn(hi_, b_); \
    float u_  = __fsub_rn(t2_, hi_); \
    float e_  = __fsub_rn(b_, u_); \
    hi_ = t2_; \
    lo_ = __fadd_rn(lo_, e_); \
} while (0)

// ---------------------------------------------------------------
// Build normalized 1D gaussian kernels in fp64, round to fp32.
// ---------------------------------------------------------------
__global__ void build_kernels_k(const float* __restrict__ sigma_list) {
    int i   = blockIdx.x;
    int tid = threadIdx.x;      // 128 threads
    float sf = sigma_list[i];
    double s = (double)sf;
    int r   = (int)floor(4.0 * s + 0.5);   // TRUNCATE=4
    int n   = 2 * r + 1;
    __shared__ double tmp[96];
    __shared__ double ssum;
    if (tid < n) {
        double mean = 0.5 * (double)(n - 1);
        double d = ((double)tid - mean) / (2.0 * s);
        tmp[tid] = exp(-(d * d));
    }
    __syncthreads();
    if (tid == 0) {
        double acc = 0.0;
        for (int j = 0; j < n; j++) acc += tmp[j];
        ssum = acc;
        d_rad[i] = r;
        d_sig[i] = sf;
    }
    __syncthreads();
    if (tid < 96) d_kx[i*96 + tid] = (tid < n) ? (float)(tmp[tid] / ssum) : 0.f;
}

// ---------------------------------------------------------------
// Horizontal pass. Symmetric pairing (a_l+a_r)*k, TWO pairs folded
// per anchored Fast2Sum (block-compensated). 4 outputs/thread.
// blockDim 128, grid (H, NS).
// ---------------------------------------------------------------
__global__ void hblur_k(const float* __restrict__ x) {
    int y  = blockIdx.x;
    int sc = blockIdx.y;
    int r  = d_rad[sc];
    int n  = 2 * r + 1;
    __shared__ float srow[W + 2*MAXR + 8];
    __shared__ float sk[96];
    int tid = threadIdx.x;
    for (int i = tid; i < W + 2*r + 4; i += 128) {
        int xx = i - r;
        srow[i] = (xx >= 0 && xx < W) ? x[y*W + xx] : 0.f;
    }
    for (int i = tid; i < n; i += 128) sk[i] = d_kx[sc*96 + i];
    __syncthreads();

    int xo = tid * 4;
    float wl[5], wr[5];
    #pragma unroll
    for (int q = 0; q < 5; q++) {
        wl[q] = srow[xo + q];
        wr[q] = srow[xo + n - 2 + q];
    }
    float hi[4] = {2.f, 2.f, 2.f, 2.f};
    float lo[4] = {0.f, 0.f, 0.f, 0.f};

    int j = 0;
    #pragma unroll 2
    for (; j + 1 < r; j += 2) {
        float k0 = sk[j], k1 = sk[j+1];
        #pragma unroll
        for (int t = 0; t < 4; t++) {
            float s1 = __fadd_rn(wl[t],   wr[t+1]);
            float b  = __fmul_rn(s1, k0);
            float s2 = __fadd_rn(wl[t+1], wr[t]);
            b = __fmaf_rn(s2, k1, b);
            F2S(hi[t], lo[t], b);
        }
        wl[0] = wl[2]; wl[1] = wl[3]; wl[2] = wl[4];
        wl[3] = srow[xo + j + 5];
        wl[4] = srow[xo + j + 6];
        wr[4] = wr[2]; wr[3] = wr[1]; wr[2] = wr[0];
        wr[0] = srow[xo + n - 4 - j];
        wr[1] = srow[xo + n - 3 - j];
    }
    if (r & 1) {
        float kj = sk[r-1];
        float kc = sk[r];
        #pragma unroll
        for (int t = 0; t < 4; t++) {
            float s = __fadd_rn(wl[t], wr[t+1]);
            float b = __fmul_rn(s, kj);
            b = __fmaf_rn(wl[t+1], kc, b);
            F2S(hi[t], lo[t], b);
        }
    } else {
        float kc = sk[r];
        #pragma unroll
        for (int t = 0; t < 4; t++) {
            float b = __fmul_rn(wl[t], kc);
            F2S(hi[t], lo[t], b);
        }
    }
    float4 o;
    o.x = __fadd_rn(__fsub_rn(hi[0], 2.f), lo[0]);
    o.y = __fadd_rn(__fsub_rn(hi[1], 2.f), lo[1]);
    o.z = __fadd_rn(__fsub_rn(hi[2], 2.f), lo[2]);
    o.w = __fadd_rn(__fsub_rn(hi[3], 2.f), lo[3]);
    *(float4*)(d_tmpf + (size_t)(sc*H + y) * W + xo) = o;
}

// ---------------------------------------------------------------
// Vertical pass, same block-compensated scheme on fp32 inputs.
// blockDim (32,8), grid (16,16,NS).
// ---------------------------------------------------------------
#define VTX 32
#define VTY 32
__global__ void vblur_k() {
    int sc = blockIdx.z;
    int x0 = blockIdx.x * VTX;
    int y0 = blockIdx.y * VTY;
    int r  = d_rad[sc];
    int n  = 2 * r + 1;
    __shared__ float tile[(VTY + 2*MAXR + 4) * VTX];
    __shared__ float sk[96];
    int tx  = threadIdx.x;
    int tid = tx + threadIdx.y * VTX;   // 256 threads
    int rows = VTY + 2 * r + 3;
    const float* inp = d_tmpf + (size_t)sc * HW;
    for (int i = tid; i < rows * VTX; i += 256) {
        int rr = i / VTX, cc = i % VTX;
        int gy = y0 - r + rr;
        tile[i] = (gy >= 0 && gy < H) ? inp[gy*W + x0 + cc] : 0.f;
    }
    for (int i = tid; i < n; i += 256) sk[i] = d_kx[sc*96 + i];
    __syncthreads();

    int yo = threadIdx.y * 4;
    float wl[5], wr[5];
    #pragma unroll
    for (int q = 0; q < 5; q++) {
        wl[q] = tile[(yo + q)*VTX + tx];
        wr[q] = tile[(yo + n - 2 + q)*VTX + tx];
    }
    float hi[4] = {2.f, 2.f, 2.f, 2.f};
    float lo[4] = {0.f, 0.f, 0.f, 0.f};

    int j = 0;
    #pragma unroll 2
    for (; j + 1 < r; j += 2) {
        float k0 = sk[j], k1 = sk[j+1];
        #pragma unroll
        for (int t = 0; t < 4; t++) {
            float s1 = __fadd_rn(wl[t],   wr[t+1]);
            float b  = __fmul_rn(s1, k0);
            float s2 = __fadd_rn(wl[t+1], wr[t]);
            b = __fmaf_rn(s2, k1, b);
            F2S(hi[t], lo[t], b);
        }
        wl[0] = wl[2]; wl[1] = wl[3]; wl[2] = wl[4];
        wl[3] = tile[(yo + j + 5)*VTX + tx];
        wl[4] = tile[(yo + j + 6)*VTX + tx];
        wr[4] = wr[2]; wr[3] = wr[1]; wr[2] = wr[0];
        wr[0] = tile[(yo + n - 4 - j)*VTX + tx];
        wr[1] = tile[(yo + n - 3 - j)*VTX + tx];
    }
    if (r & 1) {
        float kj = sk[r-1];
        float kc = sk[r];
        #pragma unroll
        for (int t = 0; t < 4; t++) {
            float s = __fadd_rn(wl[t], wr[t+1]);
            float b = __fmul_rn(s, kj);
            b = __fmaf_rn(wl[t+1], kc, b);
            F2S(hi[t], lo[t], b);
        }
    } else {
        float kc = sk[r];
        #pragma unroll
        for (int t = 0; t < 4; t++) {
            float b = __fmul_rn(wl[t], kc);
            F2S(hi[t], lo[t], b);
        }
    }
    float* outp = D_G + (size_t)sc * HW;
    #pragma unroll
    for (int t = 0; t < 4; t++)
        outp[(y0 + yo + t)*W + x0 + tx] =
            __fadd_rn(__fsub_rn(hi[t], 2.f), lo[t]);
}

// ---------------------------------------------------------------
// FUSED DoG + peak, separable max-pool, VECTORIZED fill.
// Tile cols x0-4 .. x0+131 (136 cols = 34 float4/row), 10 rows,
// all loads unclamped (guard pads make OOB reads safe; halo garbage
// only consumed as neighbors of border-excluded pixels).
// pk = (c > THRESH) && (c >= max27) == reference semantics exactly.
// blockDim (32,8), grid (4, 64, NK-2).
// ---------------------------------------------------------------
#define PTX 128
#define PTY 8
#define TC2 136
#define NV 34
__global__ void peak_k() {
    int k  = blockIdx.z + 1;            // 1..11
    int y0 = blockIdx.y * PTY;
    int x0 = blockIdx.x * PTX;
    __shared__ __align__(16) float szmax[PTY + 2][TC2];
    __shared__ __align__(16) float sdogc[PTY + 2][TC2];
    __shared__ float svmax[PTY][TC2];
    int tx = threadIdx.x;
    int ty = threadIdx.y;
    int tid = tx + ty * 32;             // 256 threads

    float sgm1 = d_sig[k-1], sg0 = d_sig[k], sgp1 = d_sig[k+1];
    const float* gm1 = D_G + (size_t)(k-1) * HW;
    const float* g0  = gm1 + HW;
    const float* gp1 = g0  + HW;
    const float* gp2 = gp1 + HW;

    // vectorized fill: 10 rows x 34 float4 = 340 vec-cells
    for (int idx = tid; idx < (PTY + 2) * NV; idx += 256) {
        int rr = idx / NV, cc = idx - rr * NV;
        int gi = (y0 - 1 + rr) * W + (x0 - 4) + cc * 4;
        float4 a = *(const float4*)(gm1 + gi);
        float4 b = *(const float4*)(g0  + gi);
        float4 c = *(const float4*)(gp1 + gi);
        float4 d = *(const float4*)(gp2 + gi);
        float4 dc, zm;
        {
            float m1 = (a.x - b.x) * sgm1;
            dc.x     = (b.x - c.x) * sg0;
            float p1 = (c.x - d.x) * sgp1;
            zm.x = fmaxf(fmaxf(m1, dc.x), p1);
        }
        {
            float m1 = (a.y - b.y) * sgm1;
            dc.y     = (b.y - c.y) * sg0;
            float p1 = (c.y - d.y) * sgp1;
            zm.y = fmaxf(fmaxf(m1, dc.y), p1);
        }
        {
            float m1 = (a.z - b.z) * sgm1;
            dc.z     = (b.z - c.z) * sg0;
            float p1 = (c.z - d.z) * sgp1;
            zm.z = fmaxf(fmaxf(m1, dc.z), p1);
        }
        {
            float m1 = (a.w - b.w) * sgm1;
            dc.w     = (b.w - c.w) * sg0;
            float p1 = (c.w - d.w) * sgp1;
            zm.w = fmaxf(fmaxf(m1, dc.w), p1);
        }
        *(float4*)&szmax[rr][cc*4] = zm;
        *(float4*)&sdogc[rr][cc*4] = dc;
    }
    __syncthreads();

    // vertical max3: row ty covers output row y0+ty (tile rows ty..ty+2)
    #pragma unroll
    for (int cc = tx; cc < TC2; cc += 32)
        svmax[ty][cc] = fmaxf(fmaxf(szmax[ty][cc], szmax[ty+1][cc]),
                              szmax[ty+2][cc]);
    __syncthreads();

    // horizontal max3 + compare; center pixel x -> tile col x-x0+4
    int y = y0 + ty;
    int cnt = 0;
    #pragma unroll
    for (int q = 0; q < 4; q++) {
        int x  = x0 + q * 32 + tx;
        int lx = q * 32 + tx + 4;
        bool pk = false;
        if (y >= 1 && y <= H-2 && x >= 1 && x <= W-2) {
            float c = sdogc[ty+1][lx];
            if (c > THRESH) {
                float m = fmaxf(fmaxf(svmax[ty][lx-1], svmax[ty][lx]),
                                svmax[ty][lx+1]);
                pk = (c >= m);
            }
        }
        unsigned wmask = __ballot_sync(0xFFFFFFFFu, pk);
        if (tx == 0) {
            d_maskw[(k*H + y)*16 + (x0/32 + q)] = wmask;
            cnt += __popc(wmask);
        }
    }
    if (tx == 0) d_pcnt[(k*H + y)*4 + blockIdx.x] = cnt;
}

// ---------------------------------------------------------------
// Count+scan over 6656 rows from the small per-block count array.
// ---------------------------------------------------------------
__global__ void scan_k() {
    const int PER = (NROWS + 1023) / 1024;   // 7
    int tid = threadIdx.x;
    int vals[PER];
    int local = 0;
    int start = tid * PER;
    #pragma unroll
    for (int j = 0; j < PER; j++) {
        int idx = start + j;
        int v = 0;
        if (idx < NROWS) {
            int4 c = *(const int4*)(d_pcnt + idx*4);
            v = c.x + c.y + c.z + c.w;
        }
        vals[j] = v;
        local += v;
    }
    __shared__ int sh[1024];
    sh[tid] = local;
    __syncthreads();
    for (int off = 1; off < 1024; off <<= 1) {
        int v = (tid >= off) ? sh[tid - off] : 0;
        __syncthreads();
        sh[tid] += v;
        __syncthreads();
    }
    int run = sh[tid] - local;
    #pragma unroll
    for (int j = 0; j < PER; j++) {
        int idx = start + j;
        if (idx < NROWS) { d_rowcnt[idx] = run; run += vals[j]; }
    }
    if (tid == 1023) d_total = sh[1023];
}

// ---------------------------------------------------------------
// Fused fill + scatter (disjoint index ranges, order-independent).
// grid NROWS blocks of 32 threads.
// ---------------------------------------------------------------
__global__ void write_k(float* __restrict__ out) {
    int rid  = blockIdx.x;
    int lane = threadIdx.x;
    int total = d_total;
    float sig0 = d_sig[0];
    #pragma unroll
    for (int j = 0; j < 5; j++) {          // 5*NROWS = 33280 >= MAXPEAKS
        int f = rid + j * NROWS;
        if (f < MAXPEAKS && f >= total && lane < 3)
            out[3*f + lane] = (lane == 0) ? sig0 : 0.f;
    }
    int k = rid >> 9, y = rid & 511;
    int run = d_rowcnt[rid];
    float sg = d_sig[k];
    for (int w = 0; w < 16; w++) {
        unsigned word = d_maskw[rid*16 + w];
        if (word) {
            if ((word >> lane) & 1u) {
                int idx = run + __popc(word & ((1u << lane) - 1u));
                if (idx < MAXPEAKS) {
                    out[3*idx]     = sg;
                    out[3*idx + 1] = (float)y;
                    out[3*idx + 2] = (float)(w*32 + lane);
                }
            }
            run += __popc(word);
        }
    }
}

extern "C" void kernel_launch(void* const* d_in, const int* in_sizes, int n_in,
                              void* d_out, int out_size) {
    const float* x     = nullptr;
    const float* sigma = nullptr;
    for (int i = 0; i < n_in; i++) {
        if (in_sizes[i] == H * W)   x     = (const float*)d_in[i];
        else if (in_sizes[i] == NS) sigma = (const float*)d_in[i];
    }
    if (!x)     x     = (const float*)d_in[0];
    if (!sigma) sigma = (const float*)d_in[n_in - 1];

    float* out = (float*)d_out;                   // [32768, 3]

    build_kernels_k<<<NS, 128>>>(sigma);
    hblur_k<<<dim3(H, NS), 128>>>(x);
    vblur_k<<<dim3(W/VTX, H/VTY, NS), dim3(VTX, 8)>>>();
    peak_k<<<dim3(W/PTX, H/PTY, NK-2), dim3(32, 8)>>>();
    scan_k<<<1, 1024>>>();
    write_k<<<NROWS, 32>>>(out);
}